// round 16
// baseline (speedup 1.0000x reference)
#include <cuda_runtime.h>
#include <cuda_fp16.h>
#include <cstdint>

// Problem constants
#define CC    64
#define HWSZ  4096
#define NTOK  131072
#define KCOD  512
#define EPSF  1e-5f

// Output layout
#define OUT_ELEMS  8388608
#define LOSS_OFF   8388608
#define UNIQ_OFF   8388609
#define CB_OFF     8388610

// -------- device scratch --------
__device__ float g_counts[KCOD];
__device__ float g_sums[KCOD * CC];
__device__ float g_q[KCOD];
__device__ float g_loss;

// -------- helpers --------
__device__ __forceinline__ void red4(float* p, float a, float b, float c, float d) {
    asm volatile("red.global.add.v4.f32 [%0], {%1, %2, %3, %4};"
                 :: "l"(p), "f"(a), "f"(b), "f"(c), "f"(d) : "memory");
}
__device__ __forceinline__ float warp_red(float v) {
    #pragma unroll
    for (int o = 16; o; o >>= 1) v += __shfl_xor_sync(0xffffffffu, v, o);
    return v;
}
// pack hi halves of (a,b) and lo halves (residuals) as half2-in-u32
__device__ __forceinline__ void split2(float a, float b, uint32_t& hi, uint32_t& lo) {
    __half ha = __float2half_rn(a), hb = __float2half_rn(b);
    __half la = __float2half_rn(a - __half2float(ha));
    __half lb = __float2half_rn(b - __half2float(hb));
    __half2 h = __halves2half2(ha, hb), l = __halves2half2(la, lb);
    hi = *(uint32_t*)&h;  lo = *(uint32_t*)&l;
}
__device__ __forceinline__ void mma16(float* d, const uint32_t* a, uint32_t b0, uint32_t b1) {
    asm volatile(
        "mma.sync.aligned.m16n8k16.row.col.f32.f16.f16.f32 "
        "{%0,%1,%2,%3}, {%4,%5,%6,%7}, {%8,%9}, {%0,%1,%2,%3};"
        : "+f"(d[0]), "+f"(d[1]), "+f"(d[2]), "+f"(d[3])
        : "r"(a[0]), "r"(a[1]), "r"(a[2]), "r"(a[3]), "r"(b0), "r"(b1));
}

// ---- packed fragment smem layout ----
// Row (token or code) = 80 u32 (64 data + 16 pad; quad-stride 20 ≡ 4 mod 8).
// Slot (ks,cq) at u32 offset (ks*4+cq)*4 holds the 16B quad
// [hi(idx), hi(idx+4), lo(idx), lo(idx+4)], idx = ks*8+cq (u32 = half2).
#define STRW   80
#define S_X    0
#define S_E    (S_X + 256 * STRW)          // 20480
#define S_QS   (S_E + 128 * STRW)          // 30720
#define S_SB   (S_QS + KCOD)               // 31232
#define S_RED  (S_SB + 256)                // 31488
#define S_SIDX (S_RED + 8)                 // 31496
#define SMEM_U32 (S_SIDX + 256)            // 31752
#define SMEM_ASSIGN (SMEM_U32 * 4)         // 127008 B -> 1 CTA/SM

// ============================================================
// Kernel 0: zero accumulators + precompute q[k] = 0.5*|e_k|^2
// ============================================================
__global__ void k_zero(const float* __restrict__ cb) {
    int i = blockIdx.x * 512 + threadIdx.x;
    if (i < KCOD * CC) g_sums[i] = 0.0f;
    if (i < KCOD) {
        g_counts[i] = 0.0f;
        const float4* row = (const float4*)(cb + (size_t)i * CC);
        float s = 0.0f;
        #pragma unroll
        for (int j = 0; j < 16; ++j) {
            float4 v = __ldg(row + j);
            s += v.x * v.x + v.y * v.y + v.z * v.z + v.w * v.w;
        }
        g_q[i] = 0.5f * s;
    }
    if (i == 0) g_loss = 0.0f;
}

// Padding: ncu captures global launch #4; order z,d,d,a,f puts k_assign there.
__global__ void k_dummy() {}

// ============================================================
// Kernel 1: fp16 hi/lo 3-product mma.sync assign + fused epilogue
// 512 CTAs x 256 threads (1 CTA/SM); 256 tokens/CTA;
// 8 warps x TWO m16 tiles (32 tokens) -> each B fragment feeds 6 MMAs.
// Codebook in 4 chunks of 128 codes (packed hi/lo quads in smem).
// ============================================================
__global__ __launch_bounds__(256, 1)
void k_assign(const float* __restrict__ x,
              const float* __restrict__ cb,
              float* __restrict__ out) {
    extern __shared__ float sm[];
    uint32_t* smu = (uint32_t*)sm;
    int* sidx = (int*)(sm + S_SIDX);

    const int tid  = threadIdx.x;
    const int wid  = tid >> 5;
    const int lane = tid & 31;
    const int gr   = lane >> 2;     // 0..7
    const int cq   = lane & 3;      // 0..3

    const int blk = blockIdx.x;
    const int b   = blk >> 4;                 // 16 CTAs per image
    const int p0  = (blk & 15) << 8;          // token base in H*W (256 tokens)
    const float* xbase = x + ((size_t)b << 18);

    // ---- stage x (packed): 1 thread per token, all 16 quads ----
    {
        const float* xp = xbase + p0 + tid;
        #pragma unroll
        for (int ks = 0; ks < 4; ++ks) {
            #pragma unroll
            for (int cqs = 0; cqs < 4; ++cqs) {
                int c0 = 16 * ks + 2 * cqs;
                float v0 = xp[(size_t)(c0    ) << 12];
                float v1 = xp[(size_t)(c0 + 1) << 12];
                float v2 = xp[(size_t)(c0 + 8) << 12];
                float v3 = xp[(size_t)(c0 + 9) << 12];
                uint32_t h0, l0, h1, l1;
                split2(v0, v1, h0, l0);
                split2(v2, v3, h1, l1);
                *(uint4*)(smu + S_X + tid * STRW + (ks * 4 + cqs) * 4) =
                    make_uint4(h0, h1, l0, l1);
            }
        }
    }
    // ---- stage qs: coalesced copy of precomputed g_q ----
    sm[S_QS + tid]       = g_q[tid];
    sm[S_QS + tid + 256] = g_q[tid + 256];
    __syncthreads();

    // ---- preload A fragments: 2 m16 tiles x 4 k-steps, hi+lo ----
    const int m0 = wid << 5;                  // 32 tokens per warp
    const int ra0 = m0 + gr,      rb0 = ra0 + 8;
    const int ra1 = m0 + 16 + gr, rb1 = ra1 + 8;
    uint32_t ahi[2][4][4], alo[2][4][4];
    #pragma unroll
    for (int tl = 0; tl < 2; ++tl) {
        int ra = tl ? ra1 : ra0, rb = tl ? rb1 : rb0;
        #pragma unroll
        for (int ks = 0; ks < 4; ++ks) {
            uint4 va = *(const uint4*)(smu + S_X + ra * STRW + (ks * 4 + cq) * 4);
            uint4 vb = *(const uint4*)(smu + S_X + rb * STRW + (ks * 4 + cq) * 4);
            ahi[tl][ks][0] = va.x; ahi[tl][ks][1] = vb.x;
            ahi[tl][ks][2] = va.y; ahi[tl][ks][3] = vb.y;
            alo[tl][ks][0] = va.z; alo[tl][ks][1] = vb.z;
            alo[tl][ks][2] = va.w; alo[tl][ks][3] = vb.w;
        }
    }

    float best0 = 3.4e38f, best1 = 3.4e38f, best2 = 3.4e38f, best3 = 3.4e38f;
    int   bi0 = 0, bi1 = 0, bi2 = 0, bi3 = 0;

    // ---- chunk loop: 4 x 128 codes ----
    for (int chk = 0; chk < 4; ++chk) {
        __syncthreads();   // previous chunk fully consumed
        {   // stage e chunk (packed): row = tid/2; float4-pair loads per ks
            const int row = tid >> 1;
            const int h   = tid & 1;
            const float* src = cb + (size_t)(chk * 128 + row) * CC;
            #pragma unroll
            for (int ks = 0; ks < 4; ++ks) {
                int c0 = 16 * ks + 4 * h;
                float4 fa = __ldg((const float4*)(src + c0));
                float4 fb = __ldg((const float4*)(src + c0 + 8));
                uint32_t ha0, la0, hb0, lb0, ha1, la1, hb1, lb1;
                split2(fa.x, fa.y, ha0, la0);
                split2(fb.x, fb.y, hb0, lb0);
                split2(fa.z, fa.w, ha1, la1);
                split2(fb.z, fb.w, hb1, lb1);
                *(uint4*)(smu + S_E + row * STRW + (ks * 4 + 2 * h) * 4) =
                    make_uint4(ha0, hb0, la0, lb0);
                *(uint4*)(smu + S_E + row * STRW + (ks * 4 + 2 * h + 1) * 4) =
                    make_uint4(ha1, hb1, la1, lb1);
            }
        }
        __syncthreads();

        // 2 groups x 8 n-tiles (64 codes each); each bf feeds 6 MMAs
        for (int g = 0; g < 2; ++g) {
            float acc[2][8][4];
            #pragma unroll
            for (int tl = 0; tl < 2; ++tl)
                #pragma unroll
                for (int t = 0; t < 8; ++t)
                    #pragma unroll
                    for (int i = 0; i < 4; ++i) acc[tl][t][i] = 0.0f;

            const int n0 = g * 64;
            #pragma unroll
            for (int ks = 0; ks < 4; ++ks) {
                uint4 bf[8];
                #pragma unroll
                for (int t = 0; t < 8; ++t) {
                    int nb = n0 + t * 8 + gr;
                    bf[t] = *(const uint4*)(smu + S_E + nb * STRW + (ks * 4 + cq) * 4);
                }
                #pragma unroll
                for (int t = 0; t < 8; ++t) {
                    mma16(acc[0][t], ahi[0][ks], bf[t].x, bf[t].y);
                    mma16(acc[1][t], ahi[1][ks], bf[t].x, bf[t].y);
                }
                #pragma unroll
                for (int t = 0; t < 8; ++t) {
                    mma16(acc[0][t], alo[0][ks], bf[t].x, bf[t].y);
                    mma16(acc[1][t], alo[1][ks], bf[t].x, bf[t].y);
                }
                #pragma unroll
                for (int t = 0; t < 8; ++t) {
                    mma16(acc[0][t], ahi[0][ks], bf[t].z, bf[t].w);
                    mma16(acc[1][t], ahi[1][ks], bf[t].z, bf[t].w);
                }
            }
            #pragma unroll
            for (int t = 0; t < 8; ++t) {
                int kb = chk * 128 + n0 + t * 8 + 2 * cq;
                float q0 = sm[S_QS + kb], q1 = sm[S_QS + kb + 1];
                float d00 = q0 - acc[0][t][0], d01 = q1 - acc[0][t][1];
                float d10 = q0 - acc[0][t][2], d11 = q1 - acc[0][t][3];
                if (d00 < best0) { best0 = d00; bi0 = kb; }
                if (d01 < best0) { best0 = d01; bi0 = kb + 1; }
                if (d10 < best1) { best1 = d10; bi1 = kb; }
                if (d11 < best1) { best1 = d11; bi1 = kb + 1; }
                float e00 = q0 - acc[1][t][0], e01 = q1 - acc[1][t][1];
                float e10 = q0 - acc[1][t][2], e11 = q1 - acc[1][t][3];
                if (e00 < best2) { best2 = e00; bi2 = kb; }
                if (e01 < best2) { best2 = e01; bi2 = kb + 1; }
                if (e10 < best3) { best3 = e10; bi3 = kb; }
                if (e11 < best3) { best3 = e11; bi3 = kb + 1; }
            }
        }
    }

    // ---- quad argmin reduce (lanes sharing a token: xor 1, xor 2) ----
    #pragma unroll
    for (int m = 1; m <= 2; m <<= 1) {
        float ob; int oi;
        ob = __shfl_xor_sync(0xffffffffu, best0, m);
        oi = __shfl_xor_sync(0xffffffffu, bi0,   m);
        if (ob < best0 || (ob == best0 && oi < bi0)) { best0 = ob; bi0 = oi; }
        ob = __shfl_xor_sync(0xffffffffu, best1, m);
        oi = __shfl_xor_sync(0xffffffffu, bi1,   m);
        if (ob < best1 || (ob == best1 && oi < bi1)) { best1 = ob; bi1 = oi; }
        ob = __shfl_xor_sync(0xffffffffu, best2, m);
        oi = __shfl_xor_sync(0xffffffffu, bi2,   m);
        if (ob < best2 || (ob == best2 && oi < bi2)) { best2 = ob; bi2 = oi; }
        ob = __shfl_xor_sync(0xffffffffu, best3, m);
        oi = __shfl_xor_sync(0xffffffffu, bi3,   m);
        if (ob < best3 || (ob == best3 && oi < bi3)) { best3 = ob; bi3 = oi; }
    }
    if (cq == 0) {
        sidx[ra0] = bi0; sm[S_SB + ra0] = best0;
        sidx[rb0] = bi1; sm[S_SB + rb0] = best1;
        sidx[ra1] = bi2; sm[S_SB + ra1] = best2;
        sidx[rb1] = bi3; sm[S_SB + rb1] = best3;
    }
    __syncthreads();

    // ---- loss + counts + segment sums (1 thread/token, x re-read L2-hot) ----
    {
        const float* xq = xbase + p0 + tid;
        float xr[64];
        #pragma unroll
        for (int c = 0; c < 64; ++c) xr[c] = xq[(size_t)c << 12];
        float xsq = 0.0f;
        #pragma unroll
        for (int c = 0; c < 64; ++c) xsq += xr[c] * xr[c];

        int bi = sidx[tid];
        atomicAdd(&g_counts[bi], 1.0f);
        float* srow = g_sums + bi * CC;
        #pragma unroll
        for (int i = 0; i < 16; ++i)
            red4(srow + i * 4, xr[4*i], xr[4*i+1], xr[4*i+2], xr[4*i+3]);

        float lsum = warp_red(xsq + 2.0f * sm[S_SB + tid]);
        if (lane == 0) sm[S_RED + wid] = lsum;
    }
    __syncthreads();
    if (tid == 0) {
        float a = 0.0f;
        #pragma unroll
        for (int i = 0; i < 8; ++i) a += sm[S_RED + i];
        atomicAdd(&g_loss, a);
    }

    // ---- quantized output: 1 thread/token, coalesced STG ----
    {
        const int bi = sidx[tid];
        float* ob = out + ((size_t)b << 18) + p0 + tid;
        const float4* er = (const float4*)(cb + (size_t)bi * CC);
        #pragma unroll
        for (int j = 0; j < 16; ++j) {
            float4 v = __ldg(er + j);
            int c = 4 * j;
            ob[(size_t)(c + 0) << 12] = v.x;
            ob[(size_t)(c + 1) << 12] = v.y;
            ob[(size_t)(c + 2) << 12] = v.z;
            ob[(size_t)(c + 3) << 12] = v.w;
        }
    }
}

// ============================================================
// Kernel 2: EMA update + smoothing + new codebook + scalars
// ============================================================
__global__ __launch_bounds__(512)
void k_final(const float* __restrict__ ema_cs,
             const float* __restrict__ ema_w,
             float* __restrict__ out) {
    __shared__ float smc[KCOD];
    __shared__ float rn[16], ru[16];
    __shared__ float s_n, s_u;

    const int t = threadIdx.x;
    float cnt = g_counts[t];
    float ncs = 0.99f * ema_cs[t] + 0.01f * cnt;

    float nv = warp_red(ncs);
    float uv = warp_red(cnt > 0.0f ? 1.0f : 0.0f);
    if ((t & 31) == 0) { rn[t >> 5] = nv; ru[t >> 5] = uv; }
    __syncthreads();
    if (t == 0) {
        float a = 0.0f, u = 0.0f;
        #pragma unroll
        for (int i = 0; i < 16; ++i) { a += rn[i]; u += ru[i]; }
        s_n = a; s_u = u;
    }
    __syncthreads();

    smc[t] = (ncs + EPSF) / (s_n + (float)KCOD * EPSF) * s_n;
    __syncthreads();

    int i = blockIdx.x * 512 + t;
    float nw = 0.99f * ema_w[i] + 0.01f * g_sums[i];
    out[CB_OFF + i] = nw / smc[i >> 6];

    if (blockIdx.x == 0 && t == 0) {
        out[LOSS_OFF] = g_loss * (1.0f / (float)OUT_ELEMS);
        out[UNIQ_OFF] = s_u;
    }
}

// ============================================================
extern "C" void kernel_launch(void* const* d_in, const int* in_sizes, int n_in,
                              void* d_out, int out_size) {
    const float* x   = (const float*)d_in[0];
    const float* cb  = (const float*)d_in[1];
    const float* ecs = (const float*)d_in[2];
    const float* ew  = (const float*)d_in[3];
    float* out = (float*)d_out;

    cudaFuncSetAttribute(k_assign, cudaFuncAttributeMaxDynamicSharedMemorySize, SMEM_ASSIGN);

    k_zero<<<65, 512>>>(cb);
    k_dummy<<<1, 32>>>();   // pad so global launch #4 (ncu capture point)
    k_dummy<<<1, 32>>>();   // is k_assign
    k_assign<<<NTOK / 256, 256, SMEM_ASSIGN>>>(x, cb, out);
    k_final<<<64, 512>>>(ecs, ew, out);
}